// round 2
// baseline (speedup 1.0000x reference)
#include <cuda_runtime.h>
#include <math.h>

// Problem constants (fixed by the dataset instance)
#define FEATD 256
#define HIDD  256
#define NHEAD 4
#define DHEAD 64
#define BATCH 4
#define SEQ   2048
#define TOK   (BATCH * SEQ)      // 8192 tokens per stream

// ---------------------------------------------------------------------------
// Scratch: one big __device__ array, partitioned by offsets (floats).
//   qk0 qk1 v0 v1 m0 m1 p0 p1 : 8 x 2M   (TOK*HID)
//   cat0 cat1 h0 h1           : 4 x 4M   (TOK*512)
// total 32M floats = 128 MB
// ---------------------------------------------------------------------------
__device__ float g_scratch[33554432];

static const size_t OFF_QK0 = 0;
static const size_t OFF_QK1 = 2097152;
static const size_t OFF_V0  = 4194304;
static const size_t OFF_V1  = 6291456;
static const size_t OFF_M0  = 8388608;
static const size_t OFF_M1  = 10485760;
static const size_t OFF_P0  = 12582912;
static const size_t OFF_P1  = 14680064;
static const size_t OFF_C0  = 16777216;
static const size_t OFF_C1  = 20971520;
static const size_t OFF_H0  = 25165824;
static const size_t OFF_H1  = 29360128;

// ---------------------------------------------------------------------------
// GEMM: C[M,N] = A[M,K] @ W[N,K]^T + bias  (torch Linear convention)
// MODE 0: + bias
// MODE 1: (acc + bias) * scale
// MODE 2: + bias + res[m,n]
// BM=BN=128, BK=16, 256 threads, 8x8 microtile per thread.
// ---------------------------------------------------------------------------
#define GBM 128
#define GBN 128
#define GBK 16

template<int MODE>
__global__ __launch_bounds__(256)
void gemm_kernel(const float* __restrict__ A, const float* __restrict__ W,
                 const float* __restrict__ bias, const float* __restrict__ res,
                 float* __restrict__ C, int M, int N, int K, float scale)
{
    __shared__ __align__(16) float As[GBK][GBM + 2];   // [k][m], pad 130: conflict-free STS/LDS
    __shared__ __align__(16) float Ws[GBK][GBN + 2];   // [k][n]

    const int tid = threadIdx.x;
    const int tx = tid & 15;          // 0..15 -> cols tx*8
    const int ty = tid >> 4;          // 0..15 -> rows ty*8
    const int m0 = blockIdx.y * GBM;
    const int n0 = blockIdx.x * GBN;

    float acc[8][8];
#pragma unroll
    for (int i = 0; i < 8; i++)
#pragma unroll
        for (int j = 0; j < 8; j++) acc[i][j] = 0.f;

    for (int k0 = 0; k0 < K; k0 += GBK) {
        // load A tile (128x16) transposed into As[k][m]
#pragma unroll
        for (int i = 0; i < 2; i++) {
            int f = tid + i * 256;            // float4 id, 0..511
            int m = f >> 2;
            int kc = (f & 3) << 2;
            float4 v = *(const float4*)&A[(size_t)(m0 + m) * K + k0 + kc];
            As[kc + 0][m] = v.x; As[kc + 1][m] = v.y;
            As[kc + 2][m] = v.z; As[kc + 3][m] = v.w;
        }
        // load W tile (128x16) transposed into Ws[k][n]
#pragma unroll
        for (int i = 0; i < 2; i++) {
            int f = tid + i * 256;
            int n = f >> 2;
            int kc = (f & 3) << 2;
            float4 v = *(const float4*)&W[(size_t)(n0 + n) * K + k0 + kc];
            Ws[kc + 0][n] = v.x; Ws[kc + 1][n] = v.y;
            Ws[kc + 2][n] = v.z; Ws[kc + 3][n] = v.w;
        }
        __syncthreads();

#pragma unroll
        for (int bk = 0; bk < GBK; bk++) {
            float a[8], b[8];
            const float2* ap = (const float2*)&As[bk][ty * 8];
            const float2* bp = (const float2*)&Ws[bk][tx * 8];
#pragma unroll
            for (int i = 0; i < 4; i++) { float2 t = ap[i]; a[2*i] = t.x; a[2*i+1] = t.y; }
#pragma unroll
            for (int j = 0; j < 4; j++) { float2 t = bp[j]; b[2*j] = t.x; b[2*j+1] = t.y; }
#pragma unroll
            for (int i = 0; i < 8; i++)
#pragma unroll
                for (int j = 0; j < 8; j++)
                    acc[i][j] = fmaf(a[i], b[j], acc[i][j]);
        }
        __syncthreads();
    }

    // epilogue
    float bb[8];
#pragma unroll
    for (int j = 0; j < 8; j += 4) {
        float4 t = *(const float4*)&bias[n0 + tx * 8 + j];
        bb[j] = t.x; bb[j+1] = t.y; bb[j+2] = t.z; bb[j+3] = t.w;
    }
#pragma unroll
    for (int i = 0; i < 8; i++) {
        const int m = m0 + ty * 8 + i;
        float v[8];
#pragma unroll
        for (int j = 0; j < 8; j++) {
            float t = acc[i][j] + bb[j];
            if (MODE == 1) t *= scale;
            v[j] = t;
        }
        if (MODE == 2) {
#pragma unroll
            for (int j = 0; j < 8; j += 4) {
                float4 r = *(const float4*)&res[(size_t)m * N + n0 + tx * 8 + j];
                v[j] += r.x; v[j+1] += r.y; v[j+2] += r.z; v[j+3] += r.w;
            }
        }
#pragma unroll
        for (int j = 0; j < 8; j += 4) {
            float4 o = make_float4(v[j], v[j+1], v[j+2], v[j+3]);
            *(float4*)&C[(size_t)m * N + n0 + tx * 8 + j] = o;
        }
    }
}

// ---------------------------------------------------------------------------
// Flash attention, fp32. Layouts are merged [B][N][HID]; head h uses cols
// h*64..h*64+63. One thread per query row (full softmax state per-thread).
// Grid: (SEQ/128, BATCH*NHEAD). 128 threads.
// ---------------------------------------------------------------------------
#define AT_TQ 128
#define AT_TK 32

__global__ __launch_bounds__(128)
void attn_kernel(const float* __restrict__ Qm, const float* __restrict__ Km,
                 const float* __restrict__ Vm, float* __restrict__ Om)
{
    __shared__ __align__(16) float Ks[AT_TK][DHEAD];
    __shared__ __align__(16) float Vs[AT_TK][DHEAD];

    const int tid = threadIdx.x;
    const int g = blockIdx.y;              // b*NHEAD + h
    const int b = g >> 2;
    const int h = g & 3;
    const size_t base = (size_t)b * SEQ * HIDD + (size_t)h * DHEAD;
    const int q = blockIdx.x * AT_TQ + tid;

    float qr[DHEAD], acc[DHEAD];
#pragma unroll
    for (int d = 0; d < DHEAD; d += 4) {
        float4 t = *(const float4*)&Qm[base + (size_t)q * HIDD + d];
        qr[d] = t.x; qr[d+1] = t.y; qr[d+2] = t.z; qr[d+3] = t.w;
        acc[d] = 0.f; acc[d+1] = 0.f; acc[d+2] = 0.f; acc[d+3] = 0.f;
    }
    float mx = -1e30f, l = 0.f;

    for (int k0 = 0; k0 < SEQ; k0 += AT_TK) {
        // load K,V tiles: 2048 floats each = 512 float4 / 128 threads = 4 each
#pragma unroll
        for (int i = 0; i < 4; i++) {
            int f = tid + i * 128;        // float4 id
            int j = f >> 4;
            int dd = (f & 15) << 2;
            *(float4*)&Ks[j][dd] = *(const float4*)&Km[base + (size_t)(k0 + j) * HIDD + dd];
            *(float4*)&Vs[j][dd] = *(const float4*)&Vm[base + (size_t)(k0 + j) * HIDD + dd];
        }
        __syncthreads();

        float s[AT_TK];
#pragma unroll
        for (int j = 0; j < AT_TK; j++) {
            float a = 0.f;
#pragma unroll
            for (int d = 0; d < DHEAD; d += 4) {
                float4 k4 = *(const float4*)&Ks[j][d];
                a = fmaf(qr[d],   k4.x, a);
                a = fmaf(qr[d+1], k4.y, a);
                a = fmaf(qr[d+2], k4.z, a);
                a = fmaf(qr[d+3], k4.w, a);
            }
            s[j] = a;
        }

        float tmax = s[0];
#pragma unroll
        for (int j = 1; j < AT_TK; j++) tmax = fmaxf(tmax, s[j]);
        float nm = fmaxf(mx, tmax);
        float corr = __expf(mx - nm);
        l *= corr;
#pragma unroll
        for (int d = 0; d < DHEAD; d++) acc[d] *= corr;

#pragma unroll
        for (int j = 0; j < AT_TK; j++) {
            float p = __expf(s[j] - nm);
            l += p;
#pragma unroll
            for (int d = 0; d < DHEAD; d += 4) {
                float4 v4 = *(const float4*)&Vs[j][d];
                acc[d]   = fmaf(p, v4.x, acc[d]);
                acc[d+1] = fmaf(p, v4.y, acc[d+1]);
                acc[d+2] = fmaf(p, v4.z, acc[d+2]);
                acc[d+3] = fmaf(p, v4.w, acc[d+3]);
            }
        }
        mx = nm;
        __syncthreads();
    }

    const float inv = 1.f / l;
#pragma unroll
    for (int d = 0; d < DHEAD; d += 4) {
        float4 o = make_float4(acc[d]*inv, acc[d+1]*inv, acc[d+2]*inv, acc[d+3]*inv);
        *(float4*)&Om[base + (size_t)q * HIDD + d] = o;
    }
}

// ---------------------------------------------------------------------------
// Concat: cat[t, 0:256] = x[t], cat[t, 256:512] = p[t]  (float4 granularity)
// ---------------------------------------------------------------------------
__global__ __launch_bounds__(256)
void concat_kernel(const float* __restrict__ x, const float* __restrict__ p,
                   float* __restrict__ cat)
{
    int i = blockIdx.x * 256 + threadIdx.x;   // float4 index over TOK*128
    int r = i >> 7;
    int c = i & 127;
    float4 v;
    if (c < 64) v = ((const float4*)x)[(size_t)r * 64 + c];
    else        v = ((const float4*)p)[(size_t)r * 64 + (c - 64)];
    ((float4*)cat)[i] = v;
}

// ---------------------------------------------------------------------------
// LayerNorm (512-wide rows) + exact GELU, in place. 128 threads per row.
// ---------------------------------------------------------------------------
__global__ __launch_bounds__(128)
void ln_gelu_kernel(float* __restrict__ h, const float* __restrict__ gamma,
                    const float* __restrict__ beta)
{
    __shared__ float red[8];
    const int tid = threadIdx.x;
    const size_t row = blockIdx.x;

    float4 v = *(const float4*)&h[row * 512 + tid * 4];
    float s  = v.x + v.y + v.z + v.w;
    float ss = v.x*v.x + v.y*v.y + v.z*v.z + v.w*v.w;
#pragma unroll
    for (int o = 16; o > 0; o >>= 1) {
        s  += __shfl_xor_sync(0xffffffffu, s,  o);
        ss += __shfl_xor_sync(0xffffffffu, ss, o);
    }
    const int w = tid >> 5;
    if ((tid & 31) == 0) { red[w] = s; red[4 + w] = ss; }
    __syncthreads();
    s  = red[0] + red[1] + red[2] + red[3];
    ss = red[4] + red[5] + red[6] + red[7];

    const float mu   = s * (1.f / 512.f);
    const float var  = ss * (1.f / 512.f) - mu * mu;
    const float rstd = rsqrtf(var + 1e-5f);

    float4 g4 = *(const float4*)&gamma[tid * 4];
    float4 b4 = *(const float4*)&beta[tid * 4];

    float y[4], gin[4] = {v.x, v.y, v.z, v.w};
    float gg[4] = {g4.x, g4.y, g4.z, g4.w};
    float bb[4] = {b4.x, b4.y, b4.z, b4.w};
    float4 out;
    float* op = (float*)&out;
#pragma unroll
    for (int i = 0; i < 4; i++) {
        y[i] = (gin[i] - mu) * rstd * gg[i] + bb[i];
        op[i] = 0.5f * y[i] * (1.f + erff(y[i] * 0.70710678118654752f));
    }
    *(float4*)&h[row * 512 + tid * 4] = out;
}

// ---------------------------------------------------------------------------
// Launch
// ---------------------------------------------------------------------------
extern "C" void kernel_launch(void* const* d_in, const int* in_sizes, int n_in,
                              void* d_out, int out_size)
{
    const float* x0    = (const float*)d_in[0];
    const float* x1    = (const float*)d_in[1];
    const float* Wqk   = (const float*)d_in[2];
    const float* bqk   = (const float*)d_in[3];
    const float* Wv    = (const float*)d_in[4];
    const float* bv    = (const float*)d_in[5];
    const float* Wp    = (const float*)d_in[6];
    const float* bp    = (const float*)d_in[7];
    const float* W1    = (const float*)d_in[8];
    const float* b1    = (const float*)d_in[9];
    const float* gamma = (const float*)d_in[10];
    const float* beta  = (const float*)d_in[11];
    const float* W2    = (const float*)d_in[12];
    const float* b2    = (const float*)d_in[13];

    float* out0 = (float*)d_out;
    float* out1 = out0 + (size_t)TOK * FEATD;

    float* sc = nullptr;
    cudaGetSymbolAddress((void**)&sc, g_scratch);
    float* qk0 = sc + OFF_QK0;
    float* qk1 = sc + OFF_QK1;
    float* v0  = sc + OFF_V0;
    float* v1  = sc + OFF_V1;
    float* m0  = sc + OFF_M0;
    float* m1  = sc + OFF_M1;
    float* p0  = sc + OFF_P0;
    float* p1  = sc + OFF_P1;
    float* c0  = sc + OFF_C0;
    float* c1  = sc + OFF_C1;
    float* h0  = sc + OFF_H0;
    float* h1  = sc + OFF_H1;

    const float qk_scale = 0.35355339059327373f;   // (DH^-0.5)^0.5 = 8^-0.5

    const dim3 g256(FEATD / GBN, TOK / GBM);       // (2, 64)
    const dim3 g512(512 / GBN,  TOK / GBM);        // (4, 64)

    // QK / V projections
    gemm_kernel<1><<<g256, 256>>>(x0, Wqk, bqk, nullptr, qk0, TOK, HIDD, FEATD, qk_scale);
    gemm_kernel<1><<<g256, 256>>>(x1, Wqk, bqk, nullptr, qk1, TOK, HIDD, FEATD, qk_scale);
    gemm_kernel<0><<<g256, 256>>>(x0, Wv,  bv,  nullptr, v0,  TOK, HIDD, FEATD, 1.f);
    gemm_kernel<0><<<g256, 256>>>(x1, Wv,  bv,  nullptr, v1,  TOK, HIDD, FEATD, 1.f);

    // Cross attention (both directions)
    const dim3 ga(SEQ / AT_TQ, BATCH * NHEAD);     // (16, 16)
    attn_kernel<<<ga, 128>>>(qk0, qk1, v1, m0);
    attn_kernel<<<ga, 128>>>(qk1, qk0, v0, m1);

    // Output projection
    gemm_kernel<0><<<g256, 256>>>(m0, Wp, bp, nullptr, p0, TOK, HIDD, HIDD, 1.f);
    gemm_kernel<0><<<g256, 256>>>(m1, Wp, bp, nullptr, p1, TOK, HIDD, HIDD, 1.f);

    // MLP: concat -> W1 -> LN+GELU -> W2 + residual
    concat_kernel<<<TOK * 128 / 256, 256>>>(x0, p0, c0);
    concat_kernel<<<TOK * 128 / 256, 256>>>(x1, p1, c1);

    gemm_kernel<0><<<g512, 256>>>(c0, W1, b1, nullptr, h0, TOK, 512, 512, 1.f);
    gemm_kernel<0><<<g512, 256>>>(c1, W1, b1, nullptr, h1, TOK, 512, 512, 1.f);

    ln_gelu_kernel<<<TOK, 128>>>(h0, gamma, beta);
    ln_gelu_kernel<<<TOK, 128>>>(h1, gamma, beta);

    gemm_kernel<2><<<g256, 256>>>(h0, W2, b2, x0, out0, TOK, FEATD, 512, 1.f);
    gemm_kernel<2><<<g256, 256>>>(h1, W2, b2, x1, out1, TOK, FEATD, 512, 1.f);
}

// round 3
// speedup vs baseline: 2.7607x; 2.7607x over previous
#include <cuda_runtime.h>
#include <math.h>
#include <stdint.h>

// Problem constants (fixed by the dataset instance)
#define FEATD 256
#define HIDD  256
#define NHEAD 4
#define DHEAD 64
#define BATCH 4
#define SEQ   2048
#define TOK   (BATCH * SEQ)      // 8192 tokens per stream

// ---------------------------------------------------------------------------
// Scratch
// ---------------------------------------------------------------------------
__device__ float g_scratch[33554432];

static const size_t OFF_QK0 = 0;
static const size_t OFF_QK1 = 2097152;
static const size_t OFF_V0  = 4194304;
static const size_t OFF_V1  = 6291456;
static const size_t OFF_M0  = 8388608;
static const size_t OFF_M1  = 10485760;
static const size_t OFF_P0  = 12582912;
static const size_t OFF_P1  = 14680064;
static const size_t OFF_C0  = 16777216;
static const size_t OFF_C1  = 20971520;
static const size_t OFF_H0  = 25165824;
static const size_t OFF_H1  = 29360128;

// ---------------------------------------------------------------------------
// tf32 helpers
// ---------------------------------------------------------------------------
__device__ __forceinline__ uint32_t f2tf(float x) {
    uint32_t r; asm("cvt.rna.tf32.f32 %0, %1;" : "=r"(r) : "f"(x)); return r;
}
__device__ __forceinline__ float tf2f(float x) {   // cvt + keep as float bits
    return __uint_as_float(f2tf(x));
}

__device__ __forceinline__ void mma8(float d[4], const uint32_t a[4],
                                     const uint32_t b[2], const float c[4]) {
    asm volatile(
        "mma.sync.aligned.m16n8k8.row.col.f32.tf32.tf32.f32 "
        "{%0,%1,%2,%3},{%4,%5,%6,%7},{%8,%9},{%10,%11,%12,%13};\n"
        : "=f"(d[0]), "=f"(d[1]), "=f"(d[2]), "=f"(d[3])
        : "r"(a[0]), "r"(a[1]), "r"(a[2]), "r"(a[3]),
          "r"(b[0]), "r"(b[1]),
          "f"(c[0]), "f"(c[1]), "f"(c[2]), "f"(c[3]));
}

// ---------------------------------------------------------------------------
// Tensor-core GEMM: C[M,N] = A[M,K] @ W[N,K]^T + bias (tf32 in, fp32 acc)
// MODE 0: +bias   MODE 1: (acc+bias)*scale   MODE 2: +bias+res
// Tiles: BM=BN=128, BK=16. 8 warps, each 32 rows x 64 cols.
// ---------------------------------------------------------------------------
template<int MODE>
__global__ __launch_bounds__(256)
void gemm_tc(const float* __restrict__ A, const float* __restrict__ W,
             const float* __restrict__ bias, const float* __restrict__ res,
             float* __restrict__ C, int M, int N, int K, float scale)
{
    __shared__ __align__(16) float As[128][20];   // [m][k], stride 20
    __shared__ __align__(16) float Ws[128][20];   // [n][k]

    const int tid  = threadIdx.x;
    const int warp = tid >> 5, lane = tid & 31;
    const int g = lane >> 2, tg = lane & 3;
    const int wm = warp >> 1, wn = warp & 1;
    const int m0 = blockIdx.y * 128, n0 = blockIdx.x * 128;

    float acc[2][8][4];
#pragma unroll
    for (int mi = 0; mi < 2; mi++)
#pragma unroll
        for (int ni = 0; ni < 8; ni++)
#pragma unroll
            for (int r = 0; r < 4; r++) acc[mi][ni][r] = 0.f;

    for (int k0 = 0; k0 < K; k0 += 16) {
#pragma unroll
        for (int i = 0; i < 2; i++) {
            int f = tid + i * 256;               // 0..511 float4 slots
            int r = f >> 2, kc = (f & 3) << 2;
            float4 va = *(const float4*)&A[(size_t)(m0 + r) * K + k0 + kc];
            float4 vw = *(const float4*)&W[(size_t)(n0 + r) * K + k0 + kc];
            float4 ta = make_float4(tf2f(va.x), tf2f(va.y), tf2f(va.z), tf2f(va.w));
            float4 tw = make_float4(tf2f(vw.x), tf2f(vw.y), tf2f(vw.z), tf2f(vw.w));
            *(float4*)&As[r][kc] = ta;
            *(float4*)&Ws[r][kc] = tw;
        }
        __syncthreads();

#pragma unroll
        for (int kk = 0; kk < 16; kk += 8) {
            uint32_t af[2][4], bf[8][2];
#pragma unroll
            for (int mi = 0; mi < 2; mi++) {
                int r = wm * 32 + mi * 16;
                af[mi][0] = __float_as_uint(As[r + g    ][kk + tg    ]);
                af[mi][1] = __float_as_uint(As[r + g + 8][kk + tg    ]);
                af[mi][2] = __float_as_uint(As[r + g    ][kk + tg + 4]);
                af[mi][3] = __float_as_uint(As[r + g + 8][kk + tg + 4]);
            }
#pragma unroll
            for (int ni = 0; ni < 8; ni++) {
                int c = wn * 64 + ni * 8;
                bf[ni][0] = __float_as_uint(Ws[c + g][kk + tg    ]);
                bf[ni][1] = __float_as_uint(Ws[c + g][kk + tg + 4]);
            }
#pragma unroll
            for (int mi = 0; mi < 2; mi++)
#pragma unroll
                for (int ni = 0; ni < 8; ni++)
                    mma8(acc[mi][ni], af[mi], bf[ni], acc[mi][ni]);
        }
        __syncthreads();
    }

    // epilogue: c0/c1 -> row g, c2/c3 -> row g+8; cols 2tg, 2tg+1
#pragma unroll
    for (int mi = 0; mi < 2; mi++) {
#pragma unroll
        for (int rr = 0; rr < 2; rr++) {
            const int m = m0 + wm * 32 + mi * 16 + g + rr * 8;
#pragma unroll
            for (int ni = 0; ni < 8; ni++) {
                const int c = n0 + wn * 64 + ni * 8 + 2 * tg;
                float2 bb = *(const float2*)&bias[c];
                float v0 = acc[mi][ni][rr * 2 + 0] + bb.x;
                float v1 = acc[mi][ni][rr * 2 + 1] + bb.y;
                if (MODE == 1) { v0 *= scale; v1 *= scale; }
                if (MODE == 2) {
                    float2 rv = *(const float2*)&res[(size_t)m * N + c];
                    v0 += rv.x; v1 += rv.y;
                }
                *(float2*)&C[(size_t)m * N + c] = make_float2(v0, v1);
            }
        }
    }
}

// ---------------------------------------------------------------------------
// Tensor-core flash attention (tf32). Merged [B][N][256] layout, head h at
// cols h*64..h*64+63. CTA: 128 q rows, 8 warps x 16 rows. Key tiles of 32.
// ---------------------------------------------------------------------------
#define ATQ 128
#define ATK 32

__global__ __launch_bounds__(256)
void attn_tc(const float* __restrict__ Qm, const float* __restrict__ Km,
             const float* __restrict__ Vm, float* __restrict__ Om)
{
    __shared__ __align__(16) float Ks[ATK][68];       // [key][d]  stride 68
    __shared__ __align__(16) float Vs[ATK][72];       // [key][d]  stride 72
    __shared__ __align__(16) float Ps[8][16][36];     // per-warp P [row][key] stride 36

    const int tid  = threadIdx.x;
    const int warp = tid >> 5, lane = tid & 31;
    const int g = lane >> 2, tg = lane & 3;
    const int bh = blockIdx.y, b = bh >> 2, h = bh & 3;
    const size_t base = (size_t)b * SEQ * HIDD + (size_t)h * DHEAD;
    const int q0 = blockIdx.x * ATQ + warp * 16;

    // Q fragments: held in registers for the whole kernel
    uint32_t qf[8][4];
#pragma unroll
    for (int kk = 0; kk < 8; kk++) {
        qf[kk][0] = f2tf(Qm[base + (size_t)(q0 + g    ) * HIDD + kk * 8 + tg    ]);
        qf[kk][1] = f2tf(Qm[base + (size_t)(q0 + g + 8) * HIDD + kk * 8 + tg    ]);
        qf[kk][2] = f2tf(Qm[base + (size_t)(q0 + g    ) * HIDD + kk * 8 + tg + 4]);
        qf[kk][3] = f2tf(Qm[base + (size_t)(q0 + g + 8) * HIDD + kk * 8 + tg + 4]);
    }

    float oa[8][4];
#pragma unroll
    for (int ni = 0; ni < 8; ni++)
#pragma unroll
        for (int r = 0; r < 4; r++) oa[ni][r] = 0.f;
    float mr0 = -1e30f, mr1 = -1e30f, l0 = 0.f, l1 = 0.f;

    for (int t = 0; t < SEQ; t += ATK) {
        // load K/V tile (32 x 64), convert to tf32
#pragma unroll
        for (int i = 0; i < 2; i++) {
            int f = tid + i * 256;                 // 0..511 float4 slots
            int key = f >> 4, dd = (f & 15) << 2;
            float4 kv = *(const float4*)&Km[base + (size_t)(t + key) * HIDD + dd];
            float4 vv = *(const float4*)&Vm[base + (size_t)(t + key) * HIDD + dd];
            *(float4*)&Ks[key][dd] = make_float4(tf2f(kv.x), tf2f(kv.y), tf2f(kv.z), tf2f(kv.w));
            *(float4*)&Vs[key][dd] = make_float4(tf2f(vv.x), tf2f(vv.y), tf2f(vv.z), tf2f(vv.w));
        }
        __syncthreads();

        // S = Q @ K^T  (m16 x n32 per warp, k=64)
        float s[4][4];
#pragma unroll
        for (int ni = 0; ni < 4; ni++)
#pragma unroll
            for (int r = 0; r < 4; r++) s[ni][r] = 0.f;
#pragma unroll
        for (int kk = 0; kk < 8; kk++) {
#pragma unroll
            for (int ni = 0; ni < 4; ni++) {
                uint32_t bf[2];
                bf[0] = __float_as_uint(Ks[ni * 8 + g][kk * 8 + tg    ]);
                bf[1] = __float_as_uint(Ks[ni * 8 + g][kk * 8 + tg + 4]);
                mma8(s[ni], qf[kk], bf, s[ni]);
            }
        }

        // online softmax (rows g and g+8; quad lanes share a row)
        float rm0 = s[0][0], rm1 = s[0][2];
#pragma unroll
        for (int ni = 0; ni < 4; ni++) {
            rm0 = fmaxf(rm0, fmaxf(s[ni][0], s[ni][1]));
            rm1 = fmaxf(rm1, fmaxf(s[ni][2], s[ni][3]));
        }
        rm0 = fmaxf(rm0, __shfl_xor_sync(0xffffffffu, rm0, 1));
        rm0 = fmaxf(rm0, __shfl_xor_sync(0xffffffffu, rm0, 2));
        rm1 = fmaxf(rm1, __shfl_xor_sync(0xffffffffu, rm1, 1));
        rm1 = fmaxf(rm1, __shfl_xor_sync(0xffffffffu, rm1, 2));

        const float nm0 = fmaxf(mr0, rm0), nm1 = fmaxf(mr1, rm1);
        const float cr0 = __expf(mr0 - nm0), cr1 = __expf(mr1 - nm1);
        l0 *= cr0; l1 *= cr1;
#pragma unroll
        for (int ni = 0; ni < 8; ni++) {
            oa[ni][0] *= cr0; oa[ni][1] *= cr0;
            oa[ni][2] *= cr1; oa[ni][3] *= cr1;
        }

        float ps0 = 0.f, ps1 = 0.f;
#pragma unroll
        for (int ni = 0; ni < 4; ni++) {
            float p0 = __expf(s[ni][0] - nm0);
            float p1 = __expf(s[ni][1] - nm0);
            float p2 = __expf(s[ni][2] - nm1);
            float p3 = __expf(s[ni][3] - nm1);
            ps0 += p0 + p1; ps1 += p2 + p3;
            *(float2*)&Ps[warp][g    ][ni * 8 + 2 * tg] = make_float2(tf2f(p0), tf2f(p1));
            *(float2*)&Ps[warp][g + 8][ni * 8 + 2 * tg] = make_float2(tf2f(p2), tf2f(p3));
        }
        ps0 += __shfl_xor_sync(0xffffffffu, ps0, 1);
        ps0 += __shfl_xor_sync(0xffffffffu, ps0, 2);
        ps1 += __shfl_xor_sync(0xffffffffu, ps1, 1);
        ps1 += __shfl_xor_sync(0xffffffffu, ps1, 2);
        l0 += ps0; l1 += ps1;
        mr0 = nm0; mr1 = nm1;
        __syncwarp();

        // O += P @ V  (m16 x n64 per warp, k=32)
#pragma unroll
        for (int ki = 0; ki < 4; ki++) {
            uint32_t af[4];
            af[0] = __float_as_uint(Ps[warp][g    ][ki * 8 + tg    ]);
            af[1] = __float_as_uint(Ps[warp][g + 8][ki * 8 + tg    ]);
            af[2] = __float_as_uint(Ps[warp][g    ][ki * 8 + tg + 4]);
            af[3] = __float_as_uint(Ps[warp][g + 8][ki * 8 + tg + 4]);
#pragma unroll
            for (int ni = 0; ni < 8; ni++) {
                uint32_t bf[2];
                bf[0] = __float_as_uint(Vs[ki * 8 + tg    ][ni * 8 + g]);
                bf[1] = __float_as_uint(Vs[ki * 8 + tg + 4][ni * 8 + g]);
                mma8(oa[ni], af, bf, oa[ni]);
            }
        }
        __syncthreads();
    }

    const float inv0 = 1.f / l0, inv1 = 1.f / l1;
#pragma unroll
    for (int ni = 0; ni < 8; ni++) {
        *(float2*)&Om[base + (size_t)(q0 + g    ) * HIDD + ni * 8 + 2 * tg] =
            make_float2(oa[ni][0] * inv0, oa[ni][1] * inv0);
        *(float2*)&Om[base + (size_t)(q0 + g + 8) * HIDD + ni * 8 + 2 * tg] =
            make_float2(oa[ni][2] * inv1, oa[ni][3] * inv1);
    }
}

// ---------------------------------------------------------------------------
// Concat: cat[t, 0:256] = x[t], cat[t, 256:512] = p[t]
// ---------------------------------------------------------------------------
__global__ __launch_bounds__(256)
void concat_kernel(const float* __restrict__ x, const float* __restrict__ p,
                   float* __restrict__ cat)
{
    int i = blockIdx.x * 256 + threadIdx.x;   // float4 index over TOK*128
    int r = i >> 7;
    int c = i & 127;
    float4 v;
    if (c < 64) v = ((const float4*)x)[(size_t)r * 64 + c];
    else        v = ((const float4*)p)[(size_t)r * 64 + (c - 64)];
    ((float4*)cat)[i] = v;
}

// ---------------------------------------------------------------------------
// LayerNorm (512-wide rows) + exact GELU, in place.
// ---------------------------------------------------------------------------
__global__ __launch_bounds__(128)
void ln_gelu_kernel(float* __restrict__ h, const float* __restrict__ gamma,
                    const float* __restrict__ beta)
{
    __shared__ float red[8];
    const int tid = threadIdx.x;
    const size_t row = blockIdx.x;

    float4 v = *(const float4*)&h[row * 512 + tid * 4];
    float s  = v.x + v.y + v.z + v.w;
    float ss = v.x*v.x + v.y*v.y + v.z*v.z + v.w*v.w;
#pragma unroll
    for (int o = 16; o > 0; o >>= 1) {
        s  += __shfl_xor_sync(0xffffffffu, s,  o);
        ss += __shfl_xor_sync(0xffffffffu, ss, o);
    }
    const int w = tid >> 5;
    if ((tid & 31) == 0) { red[w] = s; red[4 + w] = ss; }
    __syncthreads();
    s  = red[0] + red[1] + red[2] + red[3];
    ss = red[4] + red[5] + red[6] + red[7];

    const float mu   = s * (1.f / 512.f);
    const float var  = ss * (1.f / 512.f) - mu * mu;
    const float rstd = rsqrtf(var + 1e-5f);

    float4 g4 = *(const float4*)&gamma[tid * 4];
    float4 b4 = *(const float4*)&beta[tid * 4];

    float gin[4] = {v.x, v.y, v.z, v.w};
    float gg[4] = {g4.x, g4.y, g4.z, g4.w};
    float bb[4] = {b4.x, b4.y, b4.z, b4.w};
    float4 out;
    float* op = (float*)&out;
#pragma unroll
    for (int i = 0; i < 4; i++) {
        float y = (gin[i] - mu) * rstd * gg[i] + bb[i];
        op[i] = 0.5f * y * (1.f + erff(y * 0.70710678118654752f));
    }
    *(float4*)&h[row * 512 + tid * 4] = out;
}

// ---------------------------------------------------------------------------
// Launch
// ---------------------------------------------------------------------------
extern "C" void kernel_launch(void* const* d_in, const int* in_sizes, int n_in,
                              void* d_out, int out_size)
{
    const float* x0    = (const float*)d_in[0];
    const float* x1    = (const float*)d_in[1];
    const float* Wqk   = (const float*)d_in[2];
    const float* bqk   = (const float*)d_in[3];
    const float* Wv    = (const float*)d_in[4];
    const float* bv    = (const float*)d_in[5];
    const float* Wp    = (const float*)d_in[6];
    const float* bp    = (const float*)d_in[7];
    const float* W1    = (const float*)d_in[8];
    const float* b1    = (const float*)d_in[9];
    const float* gamma = (const float*)d_in[10];
    const float* beta  = (const float*)d_in[11];
    const float* W2    = (const float*)d_in[12];
    const float* b2    = (const float*)d_in[13];

    float* out0 = (float*)d_out;
    float* out1 = out0 + (size_t)TOK * FEATD;

    float* sc = nullptr;
    cudaGetSymbolAddress((void**)&sc, g_scratch);
    float* qk0 = sc + OFF_QK0;
    float* qk1 = sc + OFF_QK1;
    float* v0  = sc + OFF_V0;
    float* v1  = sc + OFF_V1;
    float* m0  = sc + OFF_M0;
    float* m1  = sc + OFF_M1;
    float* p0  = sc + OFF_P0;
    float* p1  = sc + OFF_P1;
    float* c0  = sc + OFF_C0;
    float* c1  = sc + OFF_C1;
    float* h0  = sc + OFF_H0;
    float* h1  = sc + OFF_H1;

    const float qk_scale = 0.35355339059327373f;   // (DH^-0.5)^0.5 = 8^-0.5

    const dim3 g256(FEATD / 128, TOK / 128);       // (2, 64)
    const dim3 g512(512 / 128,  TOK / 128);        // (4, 64)

    // QK / V projections (tensor core, tf32)
    gemm_tc<1><<<g256, 256>>>(x0, Wqk, bqk, nullptr, qk0, TOK, HIDD, FEATD, qk_scale);
    gemm_tc<1><<<g256, 256>>>(x1, Wqk, bqk, nullptr, qk1, TOK, HIDD, FEATD, qk_scale);
    gemm_tc<0><<<g256, 256>>>(x0, Wv,  bv,  nullptr, v0,  TOK, HIDD, FEATD, 1.f);
    gemm_tc<0><<<g256, 256>>>(x1, Wv,  bv,  nullptr, v1,  TOK, HIDD, FEATD, 1.f);

    // Cross attention (both directions), tensor core
    const dim3 ga(SEQ / ATQ, BATCH * NHEAD);       // (16, 16)
    attn_tc<<<ga, 256>>>(qk0, qk1, v1, m0);
    attn_tc<<<ga, 256>>>(qk1, qk0, v0, m1);

    // Output projection
    gemm_tc<0><<<g256, 256>>>(m0, Wp, bp, nullptr, p0, TOK, HIDD, HIDD, 1.f);
    gemm_tc<0><<<g256, 256>>>(m1, Wp, bp, nullptr, p1, TOK, HIDD, HIDD, 1.f);

    // MLP: concat -> W1 -> LN+GELU -> W2 + residual
    concat_kernel<<<TOK * 128 / 256, 256>>>(x0, p0, c0);
    concat_kernel<<<TOK * 128 / 256, 256>>>(x1, p1, c1);

    gemm_tc<0><<<g512, 256>>>(c0, W1, b1, nullptr, h0, TOK, 512, 512, 1.f);
    gemm_tc<0><<<g512, 256>>>(c1, W1, b1, nullptr, h1, TOK, 512, 512, 1.f);

    ln_gelu_kernel<<<TOK, 128>>>(h0, gamma, beta);
    ln_gelu_kernel<<<TOK, 128>>>(h1, gamma, beta);

    gemm_tc<2><<<g256, 256>>>(h0, W2, b2, x0, out0, TOK, FEATD, 512, 1.f);
    gemm_tc<2><<<g256, 256>>>(h1, W2, b2, x1, out1, TOK, FEATD, 512, 1.f);
}

// round 4
// speedup vs baseline: 3.6428x; 1.3195x over previous
#include <cuda_runtime.h>
#include <math.h>
#include <stdint.h>

// Problem constants
#define FEATD 256
#define HIDD  256
#define NHEAD 4
#define DHEAD 64
#define BATCH 4
#define SEQ   2048
#define TOK   (BATCH * SEQ)      // 8192 tokens per stream

// ---------------------------------------------------------------------------
// Scratch
// ---------------------------------------------------------------------------
__device__ float g_scratch[33554432];

static const size_t OFF_QK0 = 0;
static const size_t OFF_QK1 = 2097152;
static const size_t OFF_V0  = 4194304;
static const size_t OFF_V1  = 6291456;
static const size_t OFF_M0  = 8388608;
static const size_t OFF_M1  = 10485760;
static const size_t OFF_P0  = 12582912;
static const size_t OFF_P1  = 14680064;
static const size_t OFF_H0  = 25165824;
static const size_t OFF_H1  = 29360128;

// ---------------------------------------------------------------------------
// helpers
// ---------------------------------------------------------------------------
__device__ __forceinline__ uint32_t f2tf(float x) {
    uint32_t r; asm("cvt.rna.tf32.f32 %0, %1;" : "=r"(r) : "f"(x)); return r;
}

__device__ __forceinline__ void mma8(float d[4], const uint32_t a[4],
                                     const uint32_t b[2], const float c[4]) {
    asm volatile(
        "mma.sync.aligned.m16n8k8.row.col.f32.tf32.tf32.f32 "
        "{%0,%1,%2,%3},{%4,%5,%6,%7},{%8,%9},{%10,%11,%12,%13};\n"
        : "=f"(d[0]), "=f"(d[1]), "=f"(d[2]), "=f"(d[3])
        : "r"(a[0]), "r"(a[1]), "r"(a[2]), "r"(a[3]),
          "r"(b[0]), "r"(b[1]),
          "f"(c[0]), "f"(c[1]), "f"(c[2]), "f"(c[3]));
}

#define CP16(dst_u32, src_ptr) \
    asm volatile("cp.async.cg.shared.global [%0], [%1], 16;\n" :: "r"(dst_u32), "l"(src_ptr))
#define CP_COMMIT() asm volatile("cp.async.commit_group;\n" ::)
#define CP_WAIT(n)  asm volatile("cp.async.wait_group %0;\n" :: "n"(n))

// ---------------------------------------------------------------------------
// Tensor-core GEMM, both streams fused, double-buffered cp.async pipeline.
// C[m,n] = concat_k(Alo[m,:Klo], Ahi[m,:K-Klo]) @ W[n,:K]^T + bias
// Stream chosen by blockIdx.y (rows >= TOK -> stream 1).
// MODE 0: +bias   MODE 1: (acc+bias)*scale   MODE 2: +bias+res
// Tiles: BM=BN=128, BK=16. 8 warps, each 32 rows x 64 cols.
// ---------------------------------------------------------------------------
template<int MODE>
__global__ __launch_bounds__(256)
void gemm_tc(const float* __restrict__ Alo0, const float* __restrict__ Alo1,
             const float* __restrict__ Ahi0, const float* __restrict__ Ahi1,
             int Klo, int lda_lo, int lda_hi,
             const float* __restrict__ W,
             const float* __restrict__ bias,
             const float* __restrict__ res0, const float* __restrict__ res1,
             float* __restrict__ C0, float* __restrict__ C1,
             int N, int K, float scale)
{
    __shared__ __align__(16) float As[2][128][20];   // [buf][m][k] stride 20
    __shared__ __align__(16) float Ws[2][128][20];   // [buf][n][k]

    const int tid  = threadIdx.x;
    const int warp = tid >> 5, lane = tid & 31;
    const int g = lane >> 2, tg = lane & 3;
    const int wm = warp >> 1, wn = warp & 1;
    const int m0g = blockIdx.y * 128;
    const int stream = (m0g >= TOK) ? 1 : 0;
    const int m0 = m0g - stream * TOK;
    const int n0 = blockIdx.x * 128;

    const float* __restrict__ Alo = stream ? Alo1 : Alo0;
    const float* __restrict__ Ahi = stream ? Ahi1 : Ahi0;

    // per-thread load slots: float4 f and f+256; r = f>>2, kc = (f&3)*4
    const int r0s = tid >> 2, kc0 = (tid & 3) << 2;
    const int r1s = r0s + 64;

    const int nst = K / 16;

    auto load_stage = [&](int ks, int buf) {
        const int kbase = ks * 16;
        const float* Ab; int lda, ka;
        if (kbase < Klo) { Ab = Alo; lda = lda_lo; ka = kbase; }
        else             { Ab = Ahi; lda = lda_hi; ka = kbase - Klo; }
        uint32_t d;
        d = (uint32_t)__cvta_generic_to_shared(&As[buf][r0s][kc0]);
        CP16(d, Ab + (size_t)(m0 + r0s) * lda + ka + kc0);
        d = (uint32_t)__cvta_generic_to_shared(&As[buf][r1s][kc0]);
        CP16(d, Ab + (size_t)(m0 + r1s) * lda + ka + kc0);
        d = (uint32_t)__cvta_generic_to_shared(&Ws[buf][r0s][kc0]);
        CP16(d, W + (size_t)(n0 + r0s) * K + kbase + kc0);
        d = (uint32_t)__cvta_generic_to_shared(&Ws[buf][r1s][kc0]);
        CP16(d, W + (size_t)(n0 + r1s) * K + kbase + kc0);
        CP_COMMIT();
    };

    float acc[2][8][4];
#pragma unroll
    for (int mi = 0; mi < 2; mi++)
#pragma unroll
        for (int ni = 0; ni < 8; ni++)
#pragma unroll
            for (int r = 0; r < 4; r++) acc[mi][ni][r] = 0.f;

    load_stage(0, 0);

    for (int ks = 0; ks < nst; ks++) {
        const int buf = ks & 1;
        if (ks + 1 < nst) { load_stage(ks + 1, buf ^ 1); CP_WAIT(1); }
        else              { CP_WAIT(0); }
        __syncthreads();

#pragma unroll
        for (int kk = 0; kk < 16; kk += 8) {
            uint32_t af[2][4], bf[8][2];
#pragma unroll
            for (int mi = 0; mi < 2; mi++) {
                int r = wm * 32 + mi * 16;
                af[mi][0] = __float_as_uint(As[buf][r + g    ][kk + tg    ]);
                af[mi][1] = __float_as_uint(As[buf][r + g + 8][kk + tg    ]);
                af[mi][2] = __float_as_uint(As[buf][r + g    ][kk + tg + 4]);
                af[mi][3] = __float_as_uint(As[buf][r + g + 8][kk + tg + 4]);
            }
#pragma unroll
            for (int ni = 0; ni < 8; ni++) {
                int c = wn * 64 + ni * 8;
                bf[ni][0] = __float_as_uint(Ws[buf][c + g][kk + tg    ]);
                bf[ni][1] = __float_as_uint(Ws[buf][c + g][kk + tg + 4]);
            }
#pragma unroll
            for (int mi = 0; mi < 2; mi++)
#pragma unroll
                for (int ni = 0; ni < 8; ni++)
                    mma8(acc[mi][ni], af[mi], bf[ni], acc[mi][ni]);
        }
        __syncthreads();
    }

    const float* __restrict__ res = stream ? res1 : res0;
    float* __restrict__ C = stream ? C1 : C0;

#pragma unroll
    for (int mi = 0; mi < 2; mi++) {
#pragma unroll
        for (int rr = 0; rr < 2; rr++) {
            const int m = m0 + wm * 32 + mi * 16 + g + rr * 8;
#pragma unroll
            for (int ni = 0; ni < 8; ni++) {
                const int c = n0 + wn * 64 + ni * 8 + 2 * tg;
                float2 bb = *(const float2*)&bias[c];
                float v0 = acc[mi][ni][rr * 2 + 0] + bb.x;
                float v1 = acc[mi][ni][rr * 2 + 1] + bb.y;
                if (MODE == 1) { v0 *= scale; v1 *= scale; }
                if (MODE == 2) {
                    float2 rv = *(const float2*)&res[(size_t)m * N + c];
                    v0 += rv.x; v1 += rv.y;
                }
                *(float2*)&C[(size_t)m * N + c] = make_float2(v0, v1);
            }
        }
    }
}

// ---------------------------------------------------------------------------
// Tensor-core flash attention (tf32), both directions in one launch.
// Merged [B][N][256] layout, head h at cols h*64.. CTA: 128 q rows, 8 warps.
// grid: (SEQ/128, 32) ; blockIdx.y: [0,16) dir0, [16,32) dir1.
// ---------------------------------------------------------------------------
#define ATQ 128
#define ATK 32

__global__ __launch_bounds__(256)
void attn_tc(const float* __restrict__ qk0, const float* __restrict__ qk1,
             const float* __restrict__ v0m, const float* __restrict__ v1m,
             float* __restrict__ m0m, float* __restrict__ m1m)
{
    __shared__ __align__(16) float Ks[ATK][68];       // [key][d]  stride 68
    __shared__ __align__(16) float Vs[ATK][72];       // [key][d]  stride 72
    __shared__ __align__(16) float Ps[8][16][36];     // per-warp P, stride 36

    const int tid  = threadIdx.x;
    const int warp = tid >> 5, lane = tid & 31;
    const int g = lane >> 2, tg = lane & 3;
    const int dir = blockIdx.y >> 4;
    const int bh = blockIdx.y & 15, b = bh >> 2, h = bh & 3;

    const float* __restrict__ Qm = dir ? qk1 : qk0;
    const float* __restrict__ Km = dir ? qk0 : qk1;
    const float* __restrict__ Vm = dir ? v0m : v1m;
    float* __restrict__ Om = dir ? m1m : m0m;

    const size_t base = (size_t)b * SEQ * HIDD + (size_t)h * DHEAD;
    const int q0 = blockIdx.x * ATQ + warp * 16;

    // Q fragments in registers for the whole kernel
    uint32_t qf[8][4];
#pragma unroll
    for (int kk = 0; kk < 8; kk++) {
        qf[kk][0] = f2tf(Qm[base + (size_t)(q0 + g    ) * HIDD + kk * 8 + tg    ]);
        qf[kk][1] = f2tf(Qm[base + (size_t)(q0 + g + 8) * HIDD + kk * 8 + tg    ]);
        qf[kk][2] = f2tf(Qm[base + (size_t)(q0 + g    ) * HIDD + kk * 8 + tg + 4]);
        qf[kk][3] = f2tf(Qm[base + (size_t)(q0 + g + 8) * HIDD + kk * 8 + tg + 4]);
    }

    float oa[8][4];
#pragma unroll
    for (int ni = 0; ni < 8; ni++)
#pragma unroll
        for (int r = 0; r < 4; r++) oa[ni][r] = 0.f;
    float mr0 = -1e30f, mr1 = -1e30f, l0 = 0.f, l1 = 0.f;

    // per-thread K/V load slots
    const int key0 = tid >> 4, dd0 = (tid & 15) << 2;   // slot tid
    const int key1 = key0 + 16;                         // slot tid+256

    for (int t = 0; t < SEQ; t += ATK) {
        {
            uint32_t d;
            d = (uint32_t)__cvta_generic_to_shared(&Ks[key0][dd0]);
            CP16(d, Km + base + (size_t)(t + key0) * HIDD + dd0);
            d = (uint32_t)__cvta_generic_to_shared(&Ks[key1][dd0]);
            CP16(d, Km + base + (size_t)(t + key1) * HIDD + dd0);
            d = (uint32_t)__cvta_generic_to_shared(&Vs[key0][dd0]);
            CP16(d, Vm + base + (size_t)(t + key0) * HIDD + dd0);
            d = (uint32_t)__cvta_generic_to_shared(&Vs[key1][dd0]);
            CP16(d, Vm + base + (size_t)(t + key1) * HIDD + dd0);
            CP_COMMIT();
            CP_WAIT(0);
        }
        __syncthreads();

        // S = Q @ K^T  (m16 x n32 per warp, k=64)
        float s[4][4];
#pragma unroll
        for (int ni = 0; ni < 4; ni++)
#pragma unroll
            for (int r = 0; r < 4; r++) s[ni][r] = 0.f;
#pragma unroll
        for (int kk = 0; kk < 8; kk++) {
#pragma unroll
            for (int ni = 0; ni < 4; ni++) {
                uint32_t bf[2];
                bf[0] = __float_as_uint(Ks[ni * 8 + g][kk * 8 + tg    ]);
                bf[1] = __float_as_uint(Ks[ni * 8 + g][kk * 8 + tg + 4]);
                mma8(s[ni], qf[kk], bf, s[ni]);
            }
        }

        // online softmax (rows g and g+8; quad lanes share a row)
        float rm0 = s[0][0], rm1 = s[0][2];
#pragma unroll
        for (int ni = 0; ni < 4; ni++) {
            rm0 = fmaxf(rm0, fmaxf(s[ni][0], s[ni][1]));
            rm1 = fmaxf(rm1, fmaxf(s[ni][2], s[ni][3]));
        }
        rm0 = fmaxf(rm0, __shfl_xor_sync(0xffffffffu, rm0, 1));
        rm0 = fmaxf(rm0, __shfl_xor_sync(0xffffffffu, rm0, 2));
        rm1 = fmaxf(rm1, __shfl_xor_sync(0xffffffffu, rm1, 1));
        rm1 = fmaxf(rm1, __shfl_xor_sync(0xffffffffu, rm1, 2));

        const float nm0 = fmaxf(mr0, rm0), nm1 = fmaxf(mr1, rm1);
        const float cr0 = __expf(mr0 - nm0), cr1 = __expf(mr1 - nm1);
        l0 *= cr0; l1 *= cr1;
#pragma unroll
        for (int ni = 0; ni < 8; ni++) {
            oa[ni][0] *= cr0; oa[ni][1] *= cr0;
            oa[ni][2] *= cr1; oa[ni][3] *= cr1;
        }

        float ps0 = 0.f, ps1 = 0.f;
#pragma unroll
        for (int ni = 0; ni < 4; ni++) {
            float p0 = __expf(s[ni][0] - nm0);
            float p1 = __expf(s[ni][1] - nm0);
            float p2 = __expf(s[ni][2] - nm1);
            float p3 = __expf(s[ni][3] - nm1);
            ps0 += p0 + p1; ps1 += p2 + p3;
            *(float2*)&Ps[warp][g    ][ni * 8 + 2 * tg] = make_float2(p0, p1);
            *(float2*)&Ps[warp][g + 8][ni * 8 + 2 * tg] = make_float2(p2, p3);
        }
        ps0 += __shfl_xor_sync(0xffffffffu, ps0, 1);
        ps0 += __shfl_xor_sync(0xffffffffu, ps0, 2);
        ps1 += __shfl_xor_sync(0xffffffffu, ps1, 1);
        ps1 += __shfl_xor_sync(0xffffffffu, ps1, 2);
        l0 += ps0; l1 += ps1;
        mr0 = nm0; mr1 = nm1;
        __syncwarp();

        // O += P @ V  (m16 x n64 per warp, k=32)
#pragma unroll
        for (int ki = 0; ki < 4; ki++) {
            uint32_t af[4];
            af[0] = __float_as_uint(Ps[warp][g    ][ki * 8 + tg    ]);
            af[1] = __float_as_uint(Ps[warp][g + 8][ki * 8 + tg    ]);
            af[2] = __float_as_uint(Ps[warp][g    ][ki * 8 + tg + 4]);
            af[3] = __float_as_uint(Ps[warp][g + 8][ki * 8 + tg + 4]);
#pragma unroll
            for (int ni = 0; ni < 8; ni++) {
                uint32_t bf[2];
                bf[0] = __float_as_uint(Vs[ki * 8 + tg    ][ni * 8 + g]);
                bf[1] = __float_as_uint(Vs[ki * 8 + tg + 4][ni * 8 + g]);
                mma8(oa[ni], af, bf, oa[ni]);
            }
        }
        __syncthreads();
    }

    const float inv0 = 1.f / l0, inv1 = 1.f / l1;
#pragma unroll
    for (int ni = 0; ni < 8; ni++) {
        *(float2*)&Om[base + (size_t)(q0 + g    ) * HIDD + ni * 8 + 2 * tg] =
            make_float2(oa[ni][0] * inv0, oa[ni][1] * inv0);
        *(float2*)&Om[base + (size_t)(q0 + g + 8) * HIDD + ni * 8 + 2 * tg] =
            make_float2(oa[ni][2] * inv1, oa[ni][3] * inv1);
    }
}

// ---------------------------------------------------------------------------
// LayerNorm (512-wide rows) + exact GELU, in place, both streams fused.
// ---------------------------------------------------------------------------
__global__ __launch_bounds__(128)
void ln_gelu_kernel(float* __restrict__ h0, float* __restrict__ h1,
                    const float* __restrict__ gamma, const float* __restrict__ beta)
{
    __shared__ float red[8];
    const int tid = threadIdx.x;
    const size_t row = blockIdx.x;
    float* __restrict__ h = (row < TOK) ? (h0 + row * 512) : (h1 + (row - TOK) * 512);

    float4 v = *(const float4*)&h[tid * 4];
    float s  = v.x + v.y + v.z + v.w;
    float ss = v.x*v.x + v.y*v.y + v.z*v.z + v.w*v.w;
#pragma unroll
    for (int o = 16; o > 0; o >>= 1) {
        s  += __shfl_xor_sync(0xffffffffu, s,  o);
        ss += __shfl_xor_sync(0xffffffffu, ss, o);
    }
    const int w = tid >> 5;
    if ((tid & 31) == 0) { red[w] = s; red[4 + w] = ss; }
    __syncthreads();
    s  = red[0] + red[1] + red[2] + red[3];
    ss = red[4] + red[5] + red[6] + red[7];

    const float mu   = s * (1.f / 512.f);
    const float var  = ss * (1.f / 512.f) - mu * mu;
    const float rstd = rsqrtf(var + 1e-5f);

    float4 g4 = *(const float4*)&gamma[tid * 4];
    float4 b4 = *(const float4*)&beta[tid * 4];

    float gin[4] = {v.x, v.y, v.z, v.w};
    float gg[4] = {g4.x, g4.y, g4.z, g4.w};
    float bb[4] = {b4.x, b4.y, b4.z, b4.w};
    float4 out;
    float* op = (float*)&out;
#pragma unroll
    for (int i = 0; i < 4; i++) {
        float y = (gin[i] - mu) * rstd * gg[i] + bb[i];
        op[i] = 0.5f * y * (1.f + erff(y * 0.70710678118654752f));
    }
    *(float4*)&h[tid * 4] = out;
}

// ---------------------------------------------------------------------------
// Launch
// ---------------------------------------------------------------------------
extern "C" void kernel_launch(void* const* d_in, const int* in_sizes, int n_in,
                              void* d_out, int out_size)
{
    const float* x0    = (const float*)d_in[0];
    const float* x1    = (const float*)d_in[1];
    const float* Wqk   = (const float*)d_in[2];
    const float* bqk   = (const float*)d_in[3];
    const float* Wv    = (const float*)d_in[4];
    const float* bv    = (const float*)d_in[5];
    const float* Wp    = (const float*)d_in[6];
    const float* bp    = (const float*)d_in[7];
    const float* W1    = (const float*)d_in[8];
    const float* b1    = (const float*)d_in[9];
    const float* gamma = (const float*)d_in[10];
    const float* beta  = (const float*)d_in[11];
    const float* W2    = (const float*)d_in[12];
    const float* b2    = (const float*)d_in[13];

    float* out0 = (float*)d_out;
    float* out1 = out0 + (size_t)TOK * FEATD;

    float* sc = nullptr;
    cudaGetSymbolAddress((void**)&sc, g_scratch);
    float* qk0 = sc + OFF_QK0;
    float* qk1 = sc + OFF_QK1;
    float* v0  = sc + OFF_V0;
    float* v1  = sc + OFF_V1;
    float* m0  = sc + OFF_M0;
    float* m1  = sc + OFF_M1;
    float* p0  = sc + OFF_P0;
    float* p1  = sc + OFF_P1;
    float* h0  = sc + OFF_H0;
    float* h1  = sc + OFF_H1;

    const float qk_scale = 0.35355339059327373f;   // (DH^-0.5)^0.5

    const dim3 g2(2, 2 * TOK / 128);               // (2, 256)
    const dim3 g4(4, 2 * TOK / 128);               // (4, 256)

    // QK / V projections (both streams in one launch)
    gemm_tc<1><<<g2, 256>>>(x0, x1, x0, x1, 256, 256, 256,
                            Wqk, bqk, nullptr, nullptr, qk0, qk1, 256, 256, qk_scale);
    gemm_tc<0><<<g2, 256>>>(x0, x1, x0, x1, 256, 256, 256,
                            Wv, bv, nullptr, nullptr, v0, v1, 256, 256, 1.f);

    // Cross attention, both directions in one launch
    attn_tc<<<dim3(SEQ / ATQ, 32), 256>>>(qk0, qk1, v0, v1, m0, m1);

    // Output projection
    gemm_tc<0><<<g2, 256>>>(m0, m1, m0, m1, 256, 256, 256,
                            Wp, bp, nullptr, nullptr, p0, p1, 256, 256, 1.f);

    // W1 with concat fused: A = [x | p] along k
    gemm_tc<0><<<g4, 256>>>(x0, x1, p0, p1, 256, 256, 256,
                            W1, b1, nullptr, nullptr, h0, h1, 512, 512, 1.f);

    ln_gelu_kernel<<<2 * TOK, 128>>>(h0, h1, gamma, beta);

    // W2 + residual
    gemm_tc<2><<<g2, 256>>>(h0, h1, h0, h1, 512, 512, 512,
                            W2, b2, x0, x1, out0, out1, 256, 512, 1.f);
}